// round 14
// baseline (speedup 1.0000x reference)
#include <cuda_runtime.h>
#include <cuda_bf16.h>
#include <cstdint>

// BSplineKAN, uniform knots linspace(-1,1,12), order 3, h = 2/11.
//
// Per (channel, knot-interval) the output collapses to ONE cubic in local
// coordinate t (uniform cubic B-spline matrix). Each block builds the coeff
// table in a register prologue; hot loop:
//   clamp -> magic-floor j,t -> conflict-free LDS.128 -> 3-FMA Horner.
//
// Magic floor: base = 1.5*2^23; m = fma(xx,5.5, base+5.0) = base + floor(u)
// (u in [0.055,10.945], whole range in the ulp=1 binade). j = bits(m)&15
// is PROVEN in [0,10]; NaN inputs collapse to -0.99 at the clamp.
//
// Session learnings baked in:
//  - R7: smem > 11.3 KB drops occupancy 88->57% and doubles runtime. Table
//    stays 11x64 float4 = 11,264 B -> 8 CTAs/SM (full 64-warp occupancy).
//  - R11: fp16 table decode costs ~8 fma/alu ops/elem and regresses 30%.
//    Keep fp32 table.
//  - R9: __stcs on output keeps x L2-resident across graph replays (only
//    ~81 MB/launch reaches HBM: 67 MB out + ~14 MB x misses). Keep.
//  - R12: __ldcg on x - x lines have ZERO L1 reuse (one LDG.128 consumes
//    the whole 128B line), so skipping L1 allocation removes pure fill
//    overhead from the busiest pipe (L1TEX ~65%) while preserving the
//    cross-replay L2 hit pattern.
//
// Swizzle: lane l's channels are 4*(l&15)+s. Slot (((c&3)<<4)|(c>>2)) makes
// each 8-lane LDS.128 phase tile all 32 banks for any data-dependent j.

#define NUM_CH 64
#define NUM_CP 8
#define NUM_INTERVALS 11
#define FBASE 12582912.0f             // 1.5 * 2^23

__global__ __launch_bounds__(256)
void kan_fused_kernel(const float4* __restrict__ x4,
                      const float* __restrict__ cp,
                      float4* __restrict__ out4, int nvec) {
    __shared__ float4 sco[NUM_INTERVALS * NUM_CH];   // 11,264 B, swizzled

    // ---- prologue: t-polynomial coeff table (uniform B-spline matrix /6) ----
    const float M[4][4] = {
        { 1.f/6.f, -3.f/6.f,  3.f/6.f, -1.f/6.f },
        { 4.f/6.f,  0.f,     -6.f/6.f,  3.f/6.f },
        { 1.f/6.f,  3.f/6.f,  3.f/6.f, -3.f/6.f },
        { 0.f,      0.f,      0.f,      1.f/6.f },
    };
    for (int idx = threadIdx.x; idx < NUM_INTERVALS * NUM_CH; idx += blockDim.x) {
        const int j = idx >> 6;          // 0..10
        const int c = idx & 63;
        float a0 = 0.f, a1 = 0.f, a2 = 0.f, a3 = 0.f;
#pragma unroll
        for (int k = 0; k < 4; k++) {
            const int i = j - 3 + k;
            if (i >= 0 && i < NUM_CP) {
                const float p = __ldg(&cp[c * NUM_CP + i]);
                a0 = fmaf(p, M[k][0], a0);
                a1 = fmaf(p, M[k][1], a1);
                a2 = fmaf(p, M[k][2], a2);
                a3 = fmaf(p, M[k][3], a3);
            }
        }
        const int slot = ((c & 3) << 4) | (c >> 2);   // bank-tiling swizzle
        sco[(j << 6) + slot] = make_float4(a0, a1, a2, a3);
    }
    __syncthreads();

    // ---- hot loop: 2 float4s per thread per iteration ----
    // Per-s BYTE base of (j=0, channel cbase+s); per-element address is a
    // single IMAD(j, 1024, base_s).
    const float* sco_f = (const float*)sco;
    const int cbase = (threadIdx.x << 2) & 63;
    const float* base_s[4];
#pragma unroll
    for (int s = 0; s < 4; s++) {
        const int c = cbase + s;
        base_s[s] = sco_f + 4 * (((c & 3) << 4) | (c >> 2));
    }

    const int chunk  = 2 * blockDim.x;                // 512 float4s per block-iter
    const int stride = gridDim.x * chunk;

    for (int base = blockIdx.x * chunk + threadIdx.x; base < nvec; base += stride) {
        const int v0 = base;
        const int v1 = base + (int)blockDim.x;
        const bool has1 = (v1 < nvec);

        // L2-only loads: x lines have no L1 reuse; keep L2 replay residency.
        float4 xa = __ldcg(&x4[v0]);
        float4 xb = has1 ? __ldcg(&x4[v1]) : make_float4(0.f, 0.f, 0.f, 0.f);

        float xin[8] = {xa.x, xa.y, xa.z, xa.w, xb.x, xb.y, xb.z, xb.w};
        float yo[8];
#pragma unroll
        for (int s = 0; s < 8; s++) {
            float xx = fminf(fmaxf(xin[s], -0.99f), 0.99f);
            float u  = fmaf(xx, 5.5f, 5.5f);          // in [0.055, 10.945]
            float m  = fmaf(xx, 5.5f, FBASE + 5.0f);  // = FBASE + floor(u)
            int   j  = __float_as_int(m) & 15;        // proven 0..10
            float t  = u - (m - FBASE);
            const float4 co = *(const float4*)(base_s[s & 3] + (j << 8)); // j*1024 B
            yo[s] = fmaf(fmaf(fmaf(co.w, t, co.z), t, co.y), t, co.x);
        }
        __stcs(&out4[v0], make_float4(yo[0], yo[1], yo[2], yo[3]));
        if (has1)
            __stcs(&out4[v1], make_float4(yo[4], yo[5], yo[6], yo[7]));
    }
}

extern "C" void kernel_launch(void* const* d_in, const int* in_sizes, int n_in,
                              void* d_out, int out_size) {
    const float* x  = (const float*)d_in[0];          // [262144, 64]
    const float* cp = (const float*)d_in[1];          // [64, 8]
    float* out = (float*)d_out;

    const int n = in_sizes[0];                        // B*C elements
    const int nvec = n >> 2;                          // float4 count

    const int threads = 256;
    const int blocks = 1184;                          // 148 SMs x 8 CTAs
    kan_fused_kernel<<<blocks, threads>>>((const float4*)x, cp,
                                          (float4*)out, nvec);
}

// round 16
// speedup vs baseline: 1.4490x; 1.4490x over previous
#include <cuda_runtime.h>
#include <cuda_bf16.h>
#include <cstdint>

// BSplineKAN, uniform knots linspace(-1,1,12), order 3, h = 2/11.
// FINAL (= round-9 measured best: 25.1 us total, 22.56 us eval).
//
// Per (channel, knot-interval) the output collapses to ONE cubic in local
// coordinate t (uniform cubic B-spline matrix). Each block builds the coeff
// table in a register prologue; hot loop:
//   clamp -> magic-floor j,t -> conflict-free LDS.128 -> 3-FMA Horner.
//
// Magic floor: base = 1.5*2^23; m = fma(xx,5.5, base+5.0) = base + floor(u)
// (u in [0.055,10.945], entire range inside the ulp=1 binade). j = bits&15
// is PROVEN in [0,10]; NaN inputs collapse to -0.99 at the clamp.
//
// Session ledger (why this exact shape):
//  - R2: fuse precompute + bank-tiling swizzle: 49.9 -> 26.7 us.  KEEP.
//  - R4: ILP x2 (two block-striped float4s/thread): neutral.      KEEP (harmless).
//  - R7: smem 16 KB pad -> occ 88->57%, runtime x2.  Table MUST stay 11,264 B.
//  - R8: magic floor replaces F2I/I2F: neutral on time, fewer ops. KEEP.
//  - R9: __stcs stores (keeps x L2-resident, out evict-first) + 2-op smem
//        addressing + Horner: 22.9 -> 22.6 us.                    KEEP.
//  - R11: fp16 table: decode cost >> LDS savings, -30%.           REJECTED.
//  - R14: __ldcg on x: L1TEX bypass path costs MORE, -36%.        REJECTED.
// Equilibrium: L1 ~65% / issue ~46% / DRAM ~46% at full occupancy; wavefront
// accounting puts the structural floor near this point for this layout.
//
// Swizzle proof: lane l's channels are 4*(l&15)+s. Slot (((c&3)<<4)|(c>>2))
// starts each LDS.128 at word 4*(l mod 8) mod 32, so every 8-lane phase
// tiles all 32 banks for ANY data-dependent j (j*256 words = 0 mod 32).

#define NUM_CH 64
#define NUM_CP 8
#define NUM_INTERVALS 11
#define FBASE 12582912.0f             // 1.5 * 2^23

__global__ __launch_bounds__(256)
void kan_fused_kernel(const float4* __restrict__ x4,
                      const float* __restrict__ cp,
                      float4* __restrict__ out4, int nvec) {
    __shared__ float4 sco[NUM_INTERVALS * NUM_CH];   // 11,264 B, swizzled

    // ---- prologue: t-polynomial coeff table (uniform B-spline matrix /6) ----
    const float M[4][4] = {
        { 1.f/6.f, -3.f/6.f,  3.f/6.f, -1.f/6.f },
        { 4.f/6.f,  0.f,     -6.f/6.f,  3.f/6.f },
        { 1.f/6.f,  3.f/6.f,  3.f/6.f, -3.f/6.f },
        { 0.f,      0.f,      0.f,      1.f/6.f },
    };
    for (int idx = threadIdx.x; idx < NUM_INTERVALS * NUM_CH; idx += blockDim.x) {
        const int j = idx >> 6;          // 0..10
        const int c = idx & 63;
        float a0 = 0.f, a1 = 0.f, a2 = 0.f, a3 = 0.f;
#pragma unroll
        for (int k = 0; k < 4; k++) {
            const int i = j - 3 + k;
            if (i >= 0 && i < NUM_CP) {
                const float p = __ldg(&cp[c * NUM_CP + i]);
                a0 = fmaf(p, M[k][0], a0);
                a1 = fmaf(p, M[k][1], a1);
                a2 = fmaf(p, M[k][2], a2);
                a3 = fmaf(p, M[k][3], a3);
            }
        }
        const int slot = ((c & 3) << 4) | (c >> 2);   // bank-tiling swizzle
        sco[(j << 6) + slot] = make_float4(a0, a1, a2, a3);
    }
    __syncthreads();

    // ---- hot loop: 2 float4s per thread per iteration ----
    // Per-s BYTE base of (j=0, channel cbase+s); per-element address is a
    // single IMAD(j, 1024, base_s).
    const float* sco_f = (const float*)sco;
    const int cbase = (threadIdx.x << 2) & 63;
    const float* base_s[4];
#pragma unroll
    for (int s = 0; s < 4; s++) {
        const int c = cbase + s;
        base_s[s] = sco_f + 4 * (((c & 3) << 4) | (c >> 2));
    }

    const int chunk  = 2 * blockDim.x;                // 512 float4s per block-iter
    const int stride = gridDim.x * chunk;

    for (int base = blockIdx.x * chunk + threadIdx.x; base < nvec; base += stride) {
        const int v0 = base;
        const int v1 = base + (int)blockDim.x;
        const bool has1 = (v1 < nvec);

        float4 xa = x4[v0];
        float4 xb = has1 ? x4[v1] : make_float4(0.f, 0.f, 0.f, 0.f);

        float xin[8] = {xa.x, xa.y, xa.z, xa.w, xb.x, xb.y, xb.z, xb.w};
        float yo[8];
#pragma unroll
        for (int s = 0; s < 8; s++) {
            float xx = fminf(fmaxf(xin[s], -0.99f), 0.99f);
            float u  = fmaf(xx, 5.5f, 5.5f);          // in [0.055, 10.945]
            float m  = fmaf(xx, 5.5f, FBASE + 5.0f);  // = FBASE + floor(u)
            int   j  = __float_as_int(m) & 15;        // proven 0..10
            float t  = u - (m - FBASE);
            const float4 co = *(const float4*)(base_s[s & 3] + (j << 8)); // j*1024 B
            yo[s] = fmaf(fmaf(fmaf(co.w, t, co.z), t, co.y), t, co.x);
        }
        __stcs(&out4[v0], make_float4(yo[0], yo[1], yo[2], yo[3]));
        if (has1)
            __stcs(&out4[v1], make_float4(yo[4], yo[5], yo[6], yo[7]));
    }
}

extern "C" void kernel_launch(void* const* d_in, const int* in_sizes, int n_in,
                              void* d_out, int out_size) {
    const float* x  = (const float*)d_in[0];          // [262144, 64]
    const float* cp = (const float*)d_in[1];          // [64, 8]
    float* out = (float*)d_out;

    const int n = in_sizes[0];                        // B*C elements
    const int nvec = n >> 2;                          // float4 count

    const int threads = 256;
    const int blocks = 1184;                          // 148 SMs x 8 CTAs
    kan_fused_kernel<<<blocks, threads>>>((const float4*)x, cp,
                                          (float4*)out, nvec);
}